// round 14
// baseline (speedup 1.0000x reference)
#include <cuda_runtime.h>
#include <math.h>

#define B_ 32
#define C_ 128
#define N_ 307
#define TL 12
#define TH 13
#define TMAX 13
#define LAYERS 4
#define BN_EPS 1e-5f
#define E4 921            // float4 per (b,c) row  (307*12/4)
#define NCHAIN 64
#define NTILE 16
#define PADC 132
#define ROWP 244          // staged c-row stride in floats (>= 20*12=240, 16B-mult)

// ---------------- scratch (static __device__, no allocations) ----------------
__device__ float g_Hpart [NTILE*2*4*B_*TMAX*C_]; // (nt,ch,layer,b,sl,c) 27.2 MB
__device__ float g_GWpart[NTILE*2*4*B_*TMAX*C_]; // (nt,ch,layer,b,sl,c) 27.2 MB
__device__ float g_logits[2][2*B_*TMAX*TMAX];    // double buffered per layer parity
__device__ float g_avec[2*B_*TMAX];              // final A column per (ch,b)
__device__ unsigned g_bar64_count, g_bar64_gen;  // chain-block barrier

__device__ __forceinline__ int HPidx(int nt,int ch,int i,int b){
    return ((((nt*2+ch)*4+i)*B_)+b)*TMAX*C_;
}

__device__ __forceinline__ void barrier64(){
    __threadfence();
    __syncthreads();
    if (threadIdx.x == 0){
        volatile unsigned* genp = (volatile unsigned*)&g_bar64_gen;
        unsigned g = *genp;
        if (atomicAdd(&g_bar64_count, 1u) == NCHAIN - 1u){
            atomicExch(&g_bar64_count, 0u);
            __threadfence();
            *genp = g + 1u;
        } else {
            while (*genp == g) {}
        }
    }
    __syncthreads();
}

// ==================== kernel A: X -> H partials + GW partials ================
// 256 threads/block, 1024 blocks = (b,ch) x 16 n-tiles. cp.async double-buffer.
struct __align__(16) SMa {
    float ss[2][8][ROWP];        // staged [c][n*12+s]  (8 channels per chunk)
    float4 sc2[20];
    float4 sc1[C_];
};

template<int SPAN>
__device__ __forceinline__ void phaseA(
    SMa& sm, const float4* __restrict__ X4,
    const float* __restrict__ c1, const float* __restrict__ c2,
    const float* __restrict__ w,
    int b, int ch, int nt, int n0, int tid)
{
    const int NF4 = SPAN*3;          // float4 per c-row (60 / 57)
    const int TOT = 8*NF4;           // float4 per chunk (480 / 456)
    const int pairs = SPAN*12;       // 240 / 228

    if (tid < C_)
        sm.sc1[tid] = make_float4(c1[tid], c1[C_+tid], c1[2*C_+tid], c1[3*C_+tid]);
    if (tid >= C_ && tid < C_ + SPAN){
        int nl = tid - C_;
        int n = n0 + nl;
        sm.sc2[nl] = make_float4(c2[n], c2[N_+n], c2[2*N_+n], c2[3*N_+n]);
    }

    bool actG = (tid < pairs);
    int cl = tid / 12, s12 = tid - cl*12;
    bool actH = (tid < 96);          // 8 channels/chunk: cl in [0,8)

    float ga0[4];
    #pragma unroll
    for (int i = 0; i < 4; i++) ga0[i] = 0.f;

    size_t bc = (size_t)b * C_;
    int hp0 = HPidx(nt,ch,0,b), hp1 = HPidx(nt,ch,1,b);
    int hp2 = HPidx(nt,ch,2,b), hp3 = HPidx(nt,ch,3,b);
    int slH = s12 + ch;

    auto issue = [&](int chunk){
        int bufi = chunk & 1;
        #pragma unroll
        for (int j0 = 0; j0 < TOT; j0 += 256){
            int j = j0 + tid;
            if (j < TOT){
                int c = j / NF4, r = j - c*NF4;
                const void* src = (const void*)&X4[(bc + (size_t)(chunk*8 + c))*E4 + n0*3 + r];
                unsigned dst = (unsigned)__cvta_generic_to_shared(&sm.ss[bufi][c][r*4]);
                asm volatile("cp.async.cg.shared.global [%0], [%1], 16;" :: "r"(dst), "l"(src));
            }
        }
        asm volatile("cp.async.commit_group;" ::: "memory");
    };

    issue(0);
    for (int chunk = 0; chunk < 16; chunk++){
        if (chunk < 15){
            issue(chunk + 1);
            asm volatile("cp.async.wait_group 1;" ::: "memory");
        } else {
            asm volatile("cp.async.wait_group 0;" ::: "memory");
        }
        __syncthreads();                               // S1: chunk data ready
        const float* bufp = &sm.ss[chunk & 1][0][0];

        // G: one (n,s) pair per thread, 8 channels x 4 layers
        if (actG){
            #pragma unroll
            for (int cc = 0; cc < 8; cc++){
                float4 w4 = sm.sc1[chunk*8 + cc];
                float v = bufp[cc*ROWP + tid];
                ga0[0] = fmaf(w4.x, v, ga0[0]);
                ga0[1] = fmaf(w4.y, v, ga0[1]);
                ga0[2] = fmaf(w4.z, v, ga0[2]);
                ga0[3] = fmaf(w4.w, v, ga0[3]);
            }
        }

        // H: full n-reduction per (c_local, s) thread (96 threads), unrolled
        if (actH){
            float h0 = 0.f, h1 = 0.f, h2 = 0.f, h3 = 0.f;
            const float* row = bufp + cl*ROWP + s12;
            #pragma unroll
            for (int nl = 0; nl < SPAN; nl++){
                float  v = row[nl*12];
                float4 w4 = sm.sc2[nl];
                h0 = fmaf(w4.x, v, h0);
                h1 = fmaf(w4.y, v, h1);
                h2 = fmaf(w4.z, v, h2);
                h3 = fmaf(w4.w, v, h3);
            }
            int c = chunk*8 + cl;
            g_Hpart[hp0 + slH*C_ + c] = h0;
            g_Hpart[hp1 + slH*C_ + c] = h1;
            g_Hpart[hp2 + slH*C_ + c] = h2;
            g_Hpart[hp3 + slH*C_ + c] = h3;
        }
        __syncthreads();                               // S2: buf free for reuse
    }

    if (ch && tid < C_){
        g_Hpart[hp0 + tid] = 0.f;
        g_Hpart[hp1 + tid] = 0.f;
        g_Hpart[hp2 + tid] = 0.f;
        g_Hpart[hp3 + tid] = 0.f;
    }

    // ---- fused GW partial for this n-span ----------------------------------
    float* sg = &sm.ss[0][0][0];      // 4 layers x pairs, stride ROWP
    if (actG){
        #pragma unroll
        for (int i = 0; i < 4; i++) sg[i*ROWP + tid] = ga0[i];
    }
    __syncthreads();

    {
        int c   = tid & 127;
        int il2 = tid >> 7;           // 0: layers {0,1}, 1: layers {2,3}
        #pragma unroll
        for (int i0 = 0; i0 < 2; i0++){
            int i = il2*2 + i0;
            const float* wp  = w + (size_t)i*N_*C_ + (size_t)n0*C_ + c;
            const float* sgp = sg + i*ROWP;
            float acc[12];
            #pragma unroll
            for (int s = 0; s < 12; s++) acc[s] = 0.f;
            #pragma unroll
            for (int nl = 0; nl < SPAN; nl++){
                float wv  = __ldg(wp + (size_t)nl*C_);
                float4 aa = *(const float4*)(sgp + nl*12);
                float4 bb = *(const float4*)(sgp + nl*12 + 4);
                float4 cc = *(const float4*)(sgp + nl*12 + 8);
                acc[0]  = fmaf(aa.x, wv, acc[0]);
                acc[1]  = fmaf(aa.y, wv, acc[1]);
                acc[2]  = fmaf(aa.z, wv, acc[2]);
                acc[3]  = fmaf(aa.w, wv, acc[3]);
                acc[4]  = fmaf(bb.x, wv, acc[4]);
                acc[5]  = fmaf(bb.y, wv, acc[5]);
                acc[6]  = fmaf(bb.z, wv, acc[6]);
                acc[7]  = fmaf(bb.w, wv, acc[7]);
                acc[8]  = fmaf(cc.x, wv, acc[8]);
                acc[9]  = fmaf(cc.y, wv, acc[9]);
                acc[10] = fmaf(cc.z, wv, acc[10]);
                acc[11] = fmaf(cc.w, wv, acc[11]);
            }
            int base = HPidx(nt,ch,i,b);
            #pragma unroll
            for (int s = 0; s < 12; s++)
                g_GWpart[base + (s + ch)*C_ + c] = acc[s];
            if (ch) g_GWpart[base + c] = 0.f;
        }
    }
}

__global__ void __launch_bounds__(256, 6) kA_kernel(
    const float* __restrict__ XL,  const float* __restrict__ XH,
    const float* __restrict__ c1L, const float* __restrict__ c2L,
    const float* __restrict__ wL,
    const float* __restrict__ c1H, const float* __restrict__ c2H,
    const float* __restrict__ wH)
{
    __shared__ SMa sm;
    int bid = blockIdx.x, tid = threadIdx.x;
    int group = bid >> 4, nt = bid & 15;
    int b = group >> 1, ch = group & 1;
    const float4* X4 = (const float4*)(ch ? XH : XL);
    const float* c1 = ch ? c1H : c1L;
    const float* c2 = ch ? c2H : c2L;
    const float* w  = ch ? wH  : wL;
    int n0 = nt*19 + min(nt, 3);      // tiles 0..2 span 20, 3..15 span 19
    if (nt < 3) phaseA<20>(sm, X4, c1, c2, w, b, ch, nt, n0, tid);
    else        phaseA<19>(sm, X4, c1, c2, w, b, ch, nt, n0, tid);
}

// ==================== chain kernel: 4-layer tiny attention ===================
#define CTHREADS 512

struct SMchain {
    float A[TMAX*TMAX], A2[TMAX*TMAX];
    float GWs[2][TMAX*PADC], Hs[2][TMAX*PADC];
    float f1w[TMAX*PADC], f2s[TMAX*PADC];
    float sS[TMAX*TMAX], slog[TMAX*TMAX], mu[TMAX], isd[TMAX];
};

template<int T>
__device__ __forceinline__ void load_layer(
    SMchain& sm, int bufi, int ch, int b, int i, int tid)
{
    int hp0 = HPidx(0,ch,i,b);
    const int stride = HPidx(1,ch,i,b) - hp0;   // per-nt stride (constant)
    #pragma unroll
    for (int o0 = 0; o0 < T*C_; o0 += CTHREADS){
        int o = o0 + tid;
        if (o < T*C_){
            int s = o / C_, c = o - s*C_;
            float gw = 0.f, h = 0.f;
            #pragma unroll
            for (int nt = 0; nt < NTILE; nt++){
                gw += g_GWpart[hp0 + nt*stride + o];
                h  += g_Hpart [hp0 + nt*stride + o];
            }
            sm.GWs[bufi][s*PADC + c] = gw;
            sm.Hs [bufi][s*PADC + c] = h;
        }
    }
}

template<int T>
__device__ __forceinline__ void chain_impl(
    SMchain& sm, int ch, int b,
    const float* __restrict__ bias, const float* __restrict__ vvp,
    const float* __restrict__ gam,  const float* __restrict__ bet,
    int tid)
{
    if (tid < T*T){
        int s = tid / T, t = tid - (tid/T)*T;
        sm.A[s*TMAX + t] = (s == t) ? 1.f : 0.f;
    }
    load_layer<T>(sm, 0, ch, b, 0, tid);
    __syncthreads();

    #pragma unroll
    for (int i = 0; i < LAYERS; i++){
        int bufi = i & 1;
        const float* GWs = sm.GWs[bufi];
        const float* Hs  = sm.Hs [bufi];

        #pragma unroll
        for (int o0 = 0; o0 < T*C_; o0 += CTHREADS){
            int o = o0 + tid;
            if (o < T*C_){
                int t = o / C_, c = o - (o/C_)*C_;
                float a1 = 0.f, a2 = 0.f;
                #pragma unroll
                for (int s = 0; s < T; s++){
                    float a = sm.A[s*TMAX + t];
                    a1 = fmaf(a, GWs[s*PADC + c], a1);
                    a2 = fmaf(a, Hs [s*PADC + c], a2);
                }
                sm.f1w[t*PADC + c] = a1;
                sm.f2s[t*PADC + c] = a2;
            }
        }
        __syncthreads();

        if (tid < T*T){
            int t = tid / T, q = tid - (tid/T)*T;
            float acc = bias[(i*T + t)*T + q];
            const float* f1p = &sm.f1w[t*PADC];
            const float* f2p = &sm.f2s[q*PADC];
            #pragma unroll 8
            for (int c = 0; c < C_; c++)
                acc = fmaf(f1p[c], f2p[c], acc);
            sm.sS[t*TMAX + q] = 1.f / (1.f + __expf(-acc));
        }
        __syncthreads();

        int buf = i & 1;
        if (tid < T*T){
            int t = tid / T, q = tid - (tid/T)*T;
            float acc = 0.f;
            #pragma unroll
            for (int k = 0; k < T; k++)
                acc = fmaf(vvp[(i*T + t)*T + k], sm.sS[k*TMAX + q], acc);
            sm.slog[t*TMAX + q] = acc;
            g_logits[buf][((ch*B_ + b)*TMAX + t)*TMAX + q] = acc;
        }

        if (i < LAYERS-1)
            load_layer<T>(sm, (i+1)&1, ch, b, i+1, tid);

        barrier64();

        {
            int w = tid >> 5, lane = tid & 31;
            if (w < T){
                int q = w;
                float sum = 0.f, sq = 0.f;
                #pragma unroll 4
                for (int j = lane; j < B_*T; j += 32){
                    int bb = j / T, t = j - (j/T)*T;
                    float val = __ldcg(&g_logits[buf][((ch*B_ + bb)*TMAX + t)*TMAX + q]);
                    sum += val; sq += val*val;
                }
                #pragma unroll
                for (int off = 16; off; off >>= 1){
                    sum += __shfl_down_sync(0xffffffff, sum, off);
                    sq  += __shfl_down_sync(0xffffffff, sq,  off);
                }
                if (lane == 0){
                    const float cnt = (float)(B_*T);
                    float m = sum / cnt;
                    float var = sq / cnt - m*m;
                    sm.mu[q]  = m;
                    sm.isd[q] = rsqrtf(var + BN_EPS);
                }
            }
        }
        __syncthreads();

        if (tid < T){
            int t = tid;
            float z[T];
            float mx = -1e30f;
            #pragma unroll
            for (int q = 0; q < T; q++){
                float val = (sm.slog[t*TMAX + q] - sm.mu[q]) * sm.isd[q]
                            * gam[i*T + q] + bet[i*T + q];
                z[q] = val;
                mx = fmaxf(mx, val);
            }
            float sum = 0.f;
            #pragma unroll
            for (int q = 0; q < T; q++){ z[q] = __expf(z[q] - mx); sum += z[q]; }
            float inv = 1.f / sum;
            #pragma unroll
            for (int q = 0; q < T; q++) sm.sS[t*TMAX + q] = z[q] * inv;
        }
        __syncthreads();

        if (tid < T*T){
            int s = tid / T, q = tid - (tid/T)*T;
            float acc = 0.f;
            #pragma unroll
            for (int t = 0; t < T; t++)
                acc = fmaf(sm.A[s*TMAX + t], sm.sS[q*TMAX + t], acc);
            sm.A2[s*TMAX + q] = acc;
        }
        __syncthreads();
        if (tid < T*T){
            int s = tid / T, q = tid - (tid/T)*T;
            sm.A[s*TMAX + q] = sm.A2[s*TMAX + q];
        }
        __syncthreads();
    }

    if (tid < T)
        g_avec[(ch*B_ + b)*TMAX + tid] = sm.A[tid*TMAX + (T-1)];
}

__global__ void __launch_bounds__(CTHREADS) chain_kernel(
    const float* __restrict__ bL, const float* __restrict__ vL,
    const float* __restrict__ gL, const float* __restrict__ beL,
    const float* __restrict__ bH, const float* __restrict__ vH,
    const float* __restrict__ gH, const float* __restrict__ beH)
{
    __shared__ SMchain sm;
    int bid = blockIdx.x, tid = threadIdx.x;
    int ch = bid & 1, b = bid >> 1;
    if (ch == 0) chain_impl<TL>(sm, 0, b, bL, vL, gL, beL, tid);
    else         chain_impl<TH>(sm, 1, b, bH, vH, gH, beH, tid);
}

// ==================== final kernel: residual + alpha mix =====================
__global__ void __launch_bounds__(256) final_kernel(
    const float* __restrict__ XL, const float* __restrict__ XH,
    const float* __restrict__ alpha, float* __restrict__ out)
{
    int r = blockIdx.x*blockDim.x + threadIdx.x;
    if (r >= B_*C_*N_) return;
    int b = r / (C_*N_);

    const float4* xl4 = (const float4*)(XL + (size_t)r*TL);
    const float4* xh4 = (const float4*)(XH + (size_t)r*TL);
    float4 l0 = xl4[0], l1 = xl4[1], l2 = xl4[2];
    float4 h0 = xh4[0], h1 = xh4[1], h2 = xh4[2];

    const float* aL = &g_avec[b*TMAX];
    const float* aH = &g_avec[(B_ + b)*TMAX];

    float accL = l2.w;
    accL = fmaf(l0.x, __ldg(aL+0),  accL);
    accL = fmaf(l0.y, __ldg(aL+1),  accL);
    accL = fmaf(l0.z, __ldg(aL+2),  accL);
    accL = fmaf(l0.w, __ldg(aL+3),  accL);
    accL = fmaf(l1.x, __ldg(aL+4),  accL);
    accL = fmaf(l1.y, __ldg(aL+5),  accL);
    accL = fmaf(l1.z, __ldg(aL+6),  accL);
    accL = fmaf(l1.w, __ldg(aL+7),  accL);
    accL = fmaf(l2.x, __ldg(aL+8),  accL);
    accL = fmaf(l2.y, __ldg(aL+9),  accL);
    accL = fmaf(l2.z, __ldg(aL+10), accL);
    accL = fmaf(l2.w, __ldg(aL+11), accL);

    float accH = h2.w;
    accH = fmaf(h0.x, __ldg(aH+1),  accH);
    accH = fmaf(h0.y, __ldg(aH+2),  accH);
    accH = fmaf(h0.z, __ldg(aH+3),  accH);
    accH = fmaf(h0.w, __ldg(aH+4),  accH);
    accH = fmaf(h1.x, __ldg(aH+5),  accH);
    accH = fmaf(h1.y, __ldg(aH+6),  accH);
    accH = fmaf(h1.z, __ldg(aH+7),  accH);
    accH = fmaf(h1.w, __ldg(aH+8),  accH);
    accH = fmaf(h2.x, __ldg(aH+9),  accH);
    accH = fmaf(h2.y, __ldg(aH+10), accH);
    accH = fmaf(h2.z, __ldg(aH+11), accH);
    accH = fmaf(h2.w, __ldg(aH+12), accH);

    float sa = 1.f / (1.f + expf(-alpha[0]));
    out[r] = sa*accL + (1.f - sa)*accH;
}

// ---------------- launch ----------------------------------------------------
extern "C" void kernel_launch(void* const* d_in, const int* in_sizes, int n_in,
                              void* d_out, int out_size)
{
    const float* XL  = (const float*)d_in[0];
    const float* XH  = (const float*)d_in[1];
    const float* lc1 = (const float*)d_in[2];
    const float* lc2 = (const float*)d_in[3];
    const float* lw  = (const float*)d_in[4];
    const float* lb  = (const float*)d_in[5];
    const float* lv  = (const float*)d_in[6];
    const float* lg  = (const float*)d_in[7];
    const float* lbe = (const float*)d_in[8];
    const float* hc1 = (const float*)d_in[9];
    const float* hc2 = (const float*)d_in[10];
    const float* hw  = (const float*)d_in[11];
    const float* hb  = (const float*)d_in[12];
    const float* hv  = (const float*)d_in[13];
    const float* hg  = (const float*)d_in[14];
    const float* hbe = (const float*)d_in[15];
    const float* alpha = (const float*)d_in[16];
    float* out = (float*)d_out;

    kA_kernel   <<<64*NTILE, 256>>>(XL, XH, lc1, lc2, lw, hc1, hc2, hw);
    chain_kernel<<<NCHAIN, CTHREADS>>>(lb, lv, lg, lbe, hb, hv, hg, hbe);
    int tot = B_*C_*N_;
    final_kernel<<<(tot + 255)/256, 256>>>(XL, XH, alpha, out);
}

// round 15
// speedup vs baseline: 1.1026x; 1.1026x over previous
#include <cuda_runtime.h>
#include <math.h>

#define B_ 32
#define C_ 128
#define N_ 307
#define TL 12
#define TH 13
#define TMAX 13
#define LAYERS 4
#define BN_EPS 1e-5f
#define E4 921            // float4 per (b,c) row  (307*12/4)
#define NCHAIN 64
#define NTILE 8
#define PADC 132
#define ROWPF 492         // staged c-row stride in floats (>= 39*12=468, 16B-mult)
#define ROWP4 123         // same in float4 units

// ---------------- scratch (static __device__, no allocations) ----------------
__device__ float g_Hpart [NTILE*2*4*B_*TMAX*C_]; // (nt,ch,layer,b,sl,c) 13.6 MB
__device__ float g_GWpart[NTILE*2*4*B_*TMAX*C_]; // (nt,ch,layer,b,sl,c) 13.6 MB
__device__ float g_logits[2][2*B_*TMAX*TMAX];    // double buffered per layer parity
__device__ float g_avec[2*B_*TMAX];              // final A column per (ch,b)
__device__ unsigned g_bar64_count, g_bar64_gen;  // chain-block barrier

__device__ __forceinline__ int HPidx(int nt,int ch,int i,int b){
    return ((((nt*2+ch)*4+i)*B_)+b)*TMAX*C_;
}

__device__ __forceinline__ void barrier64(){
    __threadfence();
    __syncthreads();
    if (threadIdx.x == 0){
        volatile unsigned* genp = (volatile unsigned*)&g_bar64_gen;
        unsigned g = *genp;
        if (atomicAdd(&g_bar64_count, 1u) == NCHAIN - 1u){
            atomicExch(&g_bar64_count, 0u);
            __threadfence();
            *genp = g + 1u;
        } else {
            while (*genp == g) {}
        }
    }
    __syncthreads();
}

// ==================== kernel A: X -> H partials + GW partials ================
// 256 threads/block, 512 blocks = (b,ch) x 8 n-tiles. cp.async double-buffer.
// G: warps 0-3, float4 per thread. H: warps 4-5, float2 per thread.
struct __align__(16) SMa {
    float ss[2][8][ROWPF];       // staged [c][(n-n0)*12+s]  (8 channels/chunk)
    float4 sc2[39];
    float4 sc1[C_];
};

template<int SPAN>
__device__ __forceinline__ void phaseA(
    SMa& sm, const float4* __restrict__ X4,
    const float* __restrict__ c1, const float* __restrict__ c2,
    const float* __restrict__ w,
    int b, int ch, int nt, int n0, int tid)
{
    const int NF4 = SPAN*3;          // float4 per c-row (117 / 114); also e-f4 count

    if (tid < C_)
        sm.sc1[tid] = make_float4(c1[tid], c1[C_+tid], c1[2*C_+tid], c1[3*C_+tid]);
    if (tid >= C_ && tid < C_ + SPAN){
        int nl = tid - C_;
        int n = n0 + nl;
        sm.sc2[nl] = make_float4(c2[n], c2[N_+n], c2[2*N_+n], c2[3*N_+n]);
    }

    bool actG = (tid < NF4);                    // warps 0..3 (NF4 <= 117)
    int hidx = tid - 128;
    bool actH = (hidx >= 0 && hidx < 48);       // warps 4..5
    int cl = hidx / 6, sq2 = hidx - cl*6;       // c-local, s-pair

    float4 ga[4];
    #pragma unroll
    for (int i = 0; i < 4; i++) ga[i] = make_float4(0.f,0.f,0.f,0.f);

    size_t bc = (size_t)b * C_;
    int hp0 = HPidx(nt,ch,0,b), hp1 = HPidx(nt,ch,1,b);
    int hp2 = HPidx(nt,ch,2,b), hp3 = HPidx(nt,ch,3,b);

    auto issue = [&](int chunk){
        int bufi = chunk & 1;
        const int TOT = 8*NF4;
        #pragma unroll
        for (int j0 = 0; j0 < TOT; j0 += 256){
            int j = j0 + tid;
            if (j < TOT){
                int c = j / NF4, r = j - c*NF4;
                const void* src = (const void*)&X4[(bc + (size_t)(chunk*8 + c))*E4 + n0*3 + r];
                unsigned dst = (unsigned)__cvta_generic_to_shared(&sm.ss[bufi][c][r*4]);
                asm volatile("cp.async.cg.shared.global [%0], [%1], 16;" :: "r"(dst), "l"(src));
            }
        }
        asm volatile("cp.async.commit_group;" ::: "memory");
    };

    issue(0);
    for (int chunk = 0; chunk < 16; chunk++){
        if (chunk < 15){
            issue(chunk + 1);
            asm volatile("cp.async.wait_group 1;" ::: "memory");
        } else {
            asm volatile("cp.async.wait_group 0;" ::: "memory");
        }
        __syncthreads();                               // S1: chunk data ready

        // G: float4 of e-positions per thread, 8 channels x 4 layers
        if (actG){
            const float4* buf4 = (const float4*)&sm.ss[chunk & 1][0][0];
            #pragma unroll
            for (int cc = 0; cc < 8; cc++){
                float4 w4 = sm.sc1[chunk*8 + cc];
                float4 v  = buf4[cc*ROWP4 + tid];
                ga[0].x = fmaf(w4.x, v.x, ga[0].x);
                ga[0].y = fmaf(w4.x, v.y, ga[0].y);
                ga[0].z = fmaf(w4.x, v.z, ga[0].z);
                ga[0].w = fmaf(w4.x, v.w, ga[0].w);
                ga[1].x = fmaf(w4.y, v.x, ga[1].x);
                ga[1].y = fmaf(w4.y, v.y, ga[1].y);
                ga[1].z = fmaf(w4.y, v.z, ga[1].z);
                ga[1].w = fmaf(w4.y, v.w, ga[1].w);
                ga[2].x = fmaf(w4.z, v.x, ga[2].x);
                ga[2].y = fmaf(w4.z, v.y, ga[2].y);
                ga[2].z = fmaf(w4.z, v.z, ga[2].z);
                ga[2].w = fmaf(w4.z, v.w, ga[2].w);
                ga[3].x = fmaf(w4.w, v.x, ga[3].x);
                ga[3].y = fmaf(w4.w, v.y, ga[3].y);
                ga[3].z = fmaf(w4.w, v.z, ga[3].z);
                ga[3].w = fmaf(w4.w, v.w, ga[3].w);
            }
        }

        // H: float2 of s per thread over full n-span (complete per chunk)
        if (actH){
            const float2* row2 = (const float2*)&sm.ss[chunk & 1][cl][0];
            float2 h0 = make_float2(0.f,0.f), h1 = h0, h2 = h0, h3 = h0;
            #pragma unroll
            for (int nl = 0; nl < SPAN; nl++){
                float2 v  = row2[nl*6 + sq2];
                float4 w4 = sm.sc2[nl];
                h0.x = fmaf(w4.x, v.x, h0.x);  h0.y = fmaf(w4.x, v.y, h0.y);
                h1.x = fmaf(w4.y, v.x, h1.x);  h1.y = fmaf(w4.y, v.y, h1.y);
                h2.x = fmaf(w4.z, v.x, h2.x);  h2.y = fmaf(w4.z, v.y, h2.y);
                h3.x = fmaf(w4.w, v.x, h3.x);  h3.y = fmaf(w4.w, v.y, h3.y);
            }
            int c  = chunk*8 + cl;
            int sA = sq2*2 + ch;                        // logical s of first lane
            g_Hpart[hp0 + sA*C_ + c]     = h0.x;
            g_Hpart[hp0 + (sA+1)*C_ + c] = h0.y;
            g_Hpart[hp1 + sA*C_ + c]     = h1.x;
            g_Hpart[hp1 + (sA+1)*C_ + c] = h1.y;
            g_Hpart[hp2 + sA*C_ + c]     = h2.x;
            g_Hpart[hp2 + (sA+1)*C_ + c] = h2.y;
            g_Hpart[hp3 + sA*C_ + c]     = h3.x;
            g_Hpart[hp3 + (sA+1)*C_ + c] = h3.y;
        }
        __syncthreads();                               // S2: buf free for reuse
    }

    if (ch && tid < C_){
        g_Hpart[hp0 + tid] = 0.f;
        g_Hpart[hp1 + tid] = 0.f;
        g_Hpart[hp2 + tid] = 0.f;
        g_Hpart[hp3 + tid] = 0.f;
    }

    // ---- fused GW partial for this n-span ----------------------------------
    float* sg = &sm.ss[0][0][0];      // 4 layers x (SPAN*12), stride ROWPF
    if (actG){
        float4* sg4 = (float4*)sg;
        #pragma unroll
        for (int i = 0; i < 4; i++) sg4[i*ROWP4 + tid] = ga[i];
    }
    __syncthreads();

    {
        int c   = tid & 127;
        int il2 = tid >> 7;           // 0: layers {0,1}, 1: layers {2,3}
        #pragma unroll
        for (int i0 = 0; i0 < 2; i0++){
            int i = il2*2 + i0;
            const float* wp  = w + (size_t)i*N_*C_ + (size_t)n0*C_ + c;
            const float* sgp = sg + i*ROWPF;
            float acc[12];
            #pragma unroll
            for (int s = 0; s < 12; s++) acc[s] = 0.f;
            #pragma unroll 4
            for (int nl = 0; nl < SPAN; nl++){
                float wv  = __ldg(wp + (size_t)nl*C_);
                float4 aa = *(const float4*)(sgp + nl*12);
                float4 bb = *(const float4*)(sgp + nl*12 + 4);
                float4 cc = *(const float4*)(sgp + nl*12 + 8);
                acc[0]  = fmaf(aa.x, wv, acc[0]);
                acc[1]  = fmaf(aa.y, wv, acc[1]);
                acc[2]  = fmaf(aa.z, wv, acc[2]);
                acc[3]  = fmaf(aa.w, wv, acc[3]);
                acc[4]  = fmaf(bb.x, wv, acc[4]);
                acc[5]  = fmaf(bb.y, wv, acc[5]);
                acc[6]  = fmaf(bb.z, wv, acc[6]);
                acc[7]  = fmaf(bb.w, wv, acc[7]);
                acc[8]  = fmaf(cc.x, wv, acc[8]);
                acc[9]  = fmaf(cc.y, wv, acc[9]);
                acc[10] = fmaf(cc.z, wv, acc[10]);
                acc[11] = fmaf(cc.w, wv, acc[11]);
            }
            int base = HPidx(nt,ch,i,b);
            #pragma unroll
            for (int s = 0; s < 12; s++)
                g_GWpart[base + (s + ch)*C_ + c] = acc[s];
            if (ch) g_GWpart[base + c] = 0.f;
        }
    }
}

__global__ void __launch_bounds__(256) kA_kernel(
    const float* __restrict__ XL,  const float* __restrict__ XH,
    const float* __restrict__ c1L, const float* __restrict__ c2L,
    const float* __restrict__ wL,
    const float* __restrict__ c1H, const float* __restrict__ c2H,
    const float* __restrict__ wH)
{
    __shared__ SMa sm;
    int bid = blockIdx.x, tid = threadIdx.x;
    int group = bid >> 3, nt = bid & 7;
    int b = group >> 1, ch = group & 1;
    const float4* X4 = (const float4*)(ch ? XH : XL);
    const float* c1 = ch ? c1H : c1L;
    const float* c2 = ch ? c2H : c2L;
    const float* w  = ch ? wH  : wL;
    int n0 = nt*38 + min(nt, 3);      // tiles 0..2 span 39, 3..7 span 38
    if (nt < 3) phaseA<39>(sm, X4, c1, c2, w, b, ch, nt, n0, tid);
    else        phaseA<38>(sm, X4, c1, c2, w, b, ch, nt, n0, tid);
}

// ==================== chain kernel: 4-layer tiny attention ===================
#define CTHREADS 512

struct SMchain {
    float A[TMAX*TMAX], A2[TMAX*TMAX];
    float GWs[2][TMAX*PADC], Hs[2][TMAX*PADC];
    float f1w[TMAX*PADC], f2s[TMAX*PADC];
    float sS[TMAX*TMAX], slog[TMAX*TMAX], mu[TMAX], isd[TMAX];
};

template<int T>
__device__ __forceinline__ void load_layer(
    SMchain& sm, int bufi, int ch, int b, int i, int tid)
{
    int hp0 = HPidx(0,ch,i,b);
    const int stride = HPidx(1,ch,i,b) - hp0;   // per-nt stride (constant)
    #pragma unroll
    for (int o0 = 0; o0 < T*C_; o0 += CTHREADS){
        int o = o0 + tid;
        if (o < T*C_){
            int s = o / C_, c = o - s*C_;
            float gw = 0.f, h = 0.f;
            #pragma unroll
            for (int nt = 0; nt < NTILE; nt++){
                gw += g_GWpart[hp0 + nt*stride + o];
                h  += g_Hpart [hp0 + nt*stride + o];
            }
            sm.GWs[bufi][s*PADC + c] = gw;
            sm.Hs [bufi][s*PADC + c] = h;
        }
    }
}

template<int T>
__device__ __forceinline__ void chain_impl(
    SMchain& sm, int ch, int b,
    const float* __restrict__ bias, const float* __restrict__ vvp,
    const float* __restrict__ gam,  const float* __restrict__ bet,
    int tid)
{
    if (tid < T*T){
        int s = tid / T, t = tid - (tid/T)*T;
        sm.A[s*TMAX + t] = (s == t) ? 1.f : 0.f;
    }
    load_layer<T>(sm, 0, ch, b, 0, tid);
    __syncthreads();

    #pragma unroll
    for (int i = 0; i < LAYERS; i++){
        int bufi = i & 1;
        const float* GWs = sm.GWs[bufi];
        const float* Hs  = sm.Hs [bufi];

        #pragma unroll
        for (int o0 = 0; o0 < T*C_; o0 += CTHREADS){
            int o = o0 + tid;
            if (o < T*C_){
                int t = o / C_, c = o - (o/C_)*C_;
                float a1 = 0.f, a2 = 0.f;
                #pragma unroll
                for (int s = 0; s < T; s++){
                    float a = sm.A[s*TMAX + t];
                    a1 = fmaf(a, GWs[s*PADC + c], a1);
                    a2 = fmaf(a, Hs [s*PADC + c], a2);
                }
                sm.f1w[t*PADC + c] = a1;
                sm.f2s[t*PADC + c] = a2;
            }
        }
        __syncthreads();

        // scores: 4 independent accumulator chains
        if (tid < T*T){
            int t = tid / T, q = tid - (tid/T)*T;
            const float* f1p = &sm.f1w[t*PADC];
            const float* f2p = &sm.f2s[q*PADC];
            float a0 = 0.f, a1 = 0.f, a2 = 0.f, a3 = 0.f;
            #pragma unroll 8
            for (int c0 = 0; c0 < C_; c0 += 4){
                a0 = fmaf(f1p[c0],   f2p[c0],   a0);
                a1 = fmaf(f1p[c0+1], f2p[c0+1], a1);
                a2 = fmaf(f1p[c0+2], f2p[c0+2], a2);
                a3 = fmaf(f1p[c0+3], f2p[c0+3], a3);
            }
            float acc = bias[(i*T + t)*T + q] + ((a0 + a1) + (a2 + a3));
            sm.sS[t*TMAX + q] = 1.f / (1.f + __expf(-acc));
        }
        __syncthreads();

        int buf = i & 1;
        if (tid < T*T){
            int t = tid / T, q = tid - (tid/T)*T;
            float acc = 0.f;
            #pragma unroll
            for (int k = 0; k < T; k++)
                acc = fmaf(vvp[(i*T + t)*T + k], sm.sS[k*TMAX + q], acc);
            sm.slog[t*TMAX + q] = acc;
            g_logits[buf][((ch*B_ + b)*TMAX + t)*TMAX + q] = acc;
        }

        if (i < LAYERS-1)
            load_layer<T>(sm, (i+1)&1, ch, b, i+1, tid);

        barrier64();

        {
            int w = tid >> 5, lane = tid & 31;
            if (w < T){
                int q = w;
                float sum = 0.f, sq = 0.f;
                #pragma unroll 4
                for (int j = lane; j < B_*T; j += 32){
                    int bb = j / T, t = j - (j/T)*T;
                    float val = __ldcg(&g_logits[buf][((ch*B_ + bb)*TMAX + t)*TMAX + q]);
                    sum += val; sq += val*val;
                }
                #pragma unroll
                for (int off = 16; off; off >>= 1){
                    sum += __shfl_down_sync(0xffffffff, sum, off);
                    sq  += __shfl_down_sync(0xffffffff, sq,  off);
                }
                if (lane == 0){
                    const float cnt = (float)(B_*T);
                    float m = sum / cnt;
                    float var = sq / cnt - m*m;
                    sm.mu[q]  = m;
                    sm.isd[q] = rsqrtf(var + BN_EPS);
                }
            }
        }
        __syncthreads();

        if (tid < T){
            int t = tid;
            float z[T];
            float mx = -1e30f;
            #pragma unroll
            for (int q = 0; q < T; q++){
                float val = (sm.slog[t*TMAX + q] - sm.mu[q]) * sm.isd[q]
                            * gam[i*T + q] + bet[i*T + q];
                z[q] = val;
                mx = fmaxf(mx, val);
            }
            float sum = 0.f;
            #pragma unroll
            for (int q = 0; q < T; q++){ z[q] = __expf(z[q] - mx); sum += z[q]; }
            float inv = 1.f / sum;
            #pragma unroll
            for (int q = 0; q < T; q++) sm.sS[t*TMAX + q] = z[q] * inv;
        }
        __syncthreads();

        if (tid < T*T){
            int s = tid / T, q = tid - (tid/T)*T;
            float acc = 0.f;
            #pragma unroll
            for (int t = 0; t < T; t++)
                acc = fmaf(sm.A[s*TMAX + t], sm.sS[q*TMAX + t], acc);
            sm.A2[s*TMAX + q] = acc;
        }
        __syncthreads();
        if (tid < T*T){
            int s = tid / T, q = tid - (tid/T)*T;
            sm.A[s*TMAX + q] = sm.A2[s*TMAX + q];
        }
        __syncthreads();
    }

    if (tid < T)
        g_avec[(ch*B_ + b)*TMAX + tid] = sm.A[tid*TMAX + (T-1)];
}

__global__ void __launch_bounds__(CTHREADS) chain_kernel(
    const float* __restrict__ bL, const float* __restrict__ vL,
    const float* __restrict__ gL, const float* __restrict__ beL,
    const float* __restrict__ bH, const float* __restrict__ vH,
    const float* __restrict__ gH, const float* __restrict__ beH)
{
    __shared__ SMchain sm;
    int bid = blockIdx.x, tid = threadIdx.x;
    int ch = bid & 1, b = bid >> 1;
    if (ch == 0) chain_impl<TL>(sm, 0, b, bL, vL, gL, beL, tid);
    else         chain_impl<TH>(sm, 1, b, bH, vH, gH, beH, tid);
}

// ==================== final kernel: residual + alpha mix =====================
__global__ void __launch_bounds__(256) final_kernel(
    const float* __restrict__ XL, const float* __restrict__ XH,
    const float* __restrict__ alpha, float* __restrict__ out)
{
    int r = blockIdx.x*blockDim.x + threadIdx.x;
    if (r >= B_*C_*N_) return;
    int b = r / (C_*N_);

    const float4* xl4 = (const float4*)(XL + (size_t)r*TL);
    const float4* xh4 = (const float4*)(XH + (size_t)r*TL);
    float4 l0 = xl4[0], l1 = xl4[1], l2 = xl4[2];
    float4 h0 = xh4[0], h1 = xh4[1], h2 = xh4[2];

    const float* aL = &g_avec[b*TMAX];
    const float* aH = &g_avec[(B_ + b)*TMAX];

    float accL = l2.w;
    accL = fmaf(l0.x, __ldg(aL+0),  accL);
    accL = fmaf(l0.y, __ldg(aL+1),  accL);
    accL = fmaf(l0.z, __ldg(aL+2),  accL);
    accL = fmaf(l0.w, __ldg(aL+3),  accL);
    accL = fmaf(l1.x, __ldg(aL+4),  accL);
    accL = fmaf(l1.y, __ldg(aL+5),  accL);
    accL = fmaf(l1.z, __ldg(aL+6),  accL);
    accL = fmaf(l1.w, __ldg(aL+7),  accL);
    accL = fmaf(l2.x, __ldg(aL+8),  accL);
    accL = fmaf(l2.y, __ldg(aL+9),  accL);
    accL = fmaf(l2.z, __ldg(aL+10), accL);
    accL = fmaf(l2.w, __ldg(aL+11), accL);

    float accH = h2.w;
    accH = fmaf(h0.x, __ldg(aH+1),  accH);
    accH = fmaf(h0.y, __ldg(aH+2),  accH);
    accH = fmaf(h0.z, __ldg(aH+3),  accH);
    accH = fmaf(h0.w, __ldg(aH+4),  accH);
    accH = fmaf(h1.x, __ldg(aH+5),  accH);
    accH = fmaf(h1.y, __ldg(aH+6),  accH);
    accH = fmaf(h1.z, __ldg(aH+7),  accH);
    accH = fmaf(h1.w, __ldg(aH+8),  accH);
    accH = fmaf(h2.x, __ldg(aH+9),  accH);
    accH = fmaf(h2.y, __ldg(aH+10), accH);
    accH = fmaf(h2.z, __ldg(aH+11), accH);
    accH = fmaf(h2.w, __ldg(aH+12), accH);

    float sa = 1.f / (1.f + expf(-alpha[0]));
    out[r] = sa*accL + (1.f - sa)*accH;
}

// ---------------- launch ----------------------------------------------------
extern "C" void kernel_launch(void* const* d_in, const int* in_sizes, int n_in,
                              void* d_out, int out_size)
{
    const float* XL  = (const float*)d_in[0];
    const float* XH  = (const float*)d_in[1];
    const float* lc1 = (const float*)d_in[2];
    const float* lc2 = (const float*)d_in[3];
    const float* lw  = (const float*)d_in[4];
    const float* lb  = (const float*)d_in[5];
    const float* lv  = (const float*)d_in[6];
    const float* lg  = (const float*)d_in[7];
    const float* lbe = (const float*)d_in[8];
    const float* hc1 = (const float*)d_in[9];
    const float* hc2 = (const float*)d_in[10];
    const float* hw  = (const float*)d_in[11];
    const float* hb  = (const float*)d_in[12];
    const float* hv  = (const float*)d_in[13];
    const float* hg  = (const float*)d_in[14];
    const float* hbe = (const float*)d_in[15];
    const float* alpha = (const float*)d_in[16];
    float* out = (float*)d_out;

    kA_kernel   <<<64*NTILE, 256>>>(XL, XH, lc1, lc2, lw, hc1, hc2, hw);
    chain_kernel<<<NCHAIN, CTHREADS>>>(lb, lv, lg, lbe, hb, hv, hg, hbe);
    int tot = B_*C_*N_;
    final_kernel<<<(tot + 255)/256, 256>>>(XL, XH, alpha, out);
}

// round 17
// speedup vs baseline: 1.2771x; 1.1582x over previous
#include <cuda_runtime.h>
#include <math.h>

#define B_ 32
#define C_ 128
#define N_ 307
#define TL 12
#define TH 13
#define TMAX 13
#define LAYERS 4
#define BN_EPS 1e-5f
#define E4 921            // float4 per (b,c) row  (307*12/4)
#define NCHAIN 64
#define NTILE 8
#define PADC 132
#define SSROW2 492

// ---------------- scratch (static __device__, no allocations) ----------------
__device__ __align__(16) float g_Hpart [NTILE*2*4*B_*TMAX*C_]; // (nt,ch,layer,b,sl,c)
__device__ __align__(16) float g_GWpart[NTILE*2*4*B_*TMAX*C_]; // (nt,ch,layer,b,sl,c)
__device__ __align__(16) float g_Hd [2*4*B_*TMAX*C_];          // dense
__device__ __align__(16) float g_GWd[2*4*B_*TMAX*C_];          // dense
__device__ float g_logits[2][2*B_*TMAX*TMAX];    // double buffered per layer parity
__device__ float g_avec[2*B_*TMAX];              // final A column per (ch,b)
__device__ unsigned g_bar64_count, g_bar64_gen;  // chain-block barrier

__device__ __forceinline__ int HPidx(int nt,int ch,int i,int b){
    return ((((nt*2+ch)*4+i)*B_)+b)*TMAX*C_;
}
__device__ __forceinline__ int HDidx(int ch,int i,int b){
    return (((ch*4+i)*B_)+b)*TMAX*C_;
}

__device__ __forceinline__ void barrier64(){
    __threadfence();
    __syncthreads();
    if (threadIdx.x == 0){
        volatile unsigned* genp = (volatile unsigned*)&g_bar64_gen;
        unsigned g = *genp;
        if (atomicAdd(&g_bar64_count, 1u) == NCHAIN - 1u){
            atomicExch(&g_bar64_count, 0u);
            __threadfence();
            *genp = g + 1u;
        } else {
            while (*genp == g) {}
        }
    }
    __syncthreads();
}

// ==================== kernel A (R11 config): X -> H + GW partials ============
struct __align__(16) SMa { float ss[2][8][SSROW2]; float4 sc2[39]; float4 sc1[C_]; float hred[96*4]; };

template<int SPAN>
__device__ __forceinline__ void phaseA(
    SMa& sm, const float4* __restrict__ X4,
    const float* __restrict__ c1, const float* __restrict__ c2,
    const float* __restrict__ w,
    int b, int ch, int nt, int n0, int tid)
{
    const int NF4 = SPAN*3;
    const int TOT = 8*NF4;
    const int H1  = SPAN/2;

    if (tid < C_)
        sm.sc1[tid] = make_float4(c1[tid], c1[C_+tid], c1[2*C_+tid], c1[3*C_+tid]);
    if (tid >= C_ && tid < C_ + SPAN){
        int nl = tid - C_;
        int n = n0 + nl;
        sm.sc2[nl] = make_float4(c2[n], c2[N_+n], c2[2*N_+n], c2[3*N_+n]);
    }

    const int pairs = SPAN*12;
    int hh  = tid / 96;
    int rem = tid - hh*96;
    int cl  = rem / 12, s12 = rem - cl*12;
    bool actH = (tid < 192);
    int p1 = tid + 256;
    bool act1 = (p1 < pairs);

    float ga0[4], ga1[4];
    #pragma unroll
    for (int i = 0; i < 4; i++){ ga0[i] = 0.f; ga1[i] = 0.f; }

    size_t bc = (size_t)b * C_;
    int hp0 = HPidx(nt,ch,0,b), hp1 = HPidx(nt,ch,1,b);
    int hp2 = HPidx(nt,ch,2,b), hp3 = HPidx(nt,ch,3,b);
    int slH = s12 + ch;

    auto issue = [&](int chunk){
        int bufi = chunk & 1;
        #pragma unroll
        for (int j0 = 0; j0 < TOT; j0 += 256){
            int j = j0 + tid;
            if (j < TOT){
                int c = j / NF4, r = j - c*NF4;
                const void* src = (const void*)&X4[(bc + (size_t)(chunk*8 + c))*E4 + n0*3 + r];
                unsigned dst = (unsigned)__cvta_generic_to_shared(&sm.ss[bufi][c][r*4]);
                asm volatile("cp.async.cg.shared.global [%0], [%1], 16;" :: "r"(dst), "l"(src));
            }
        }
        asm volatile("cp.async.commit_group;" ::: "memory");
    };

    issue(0);
    for (int chunk = 0; chunk < 16; chunk++){
        if (chunk < 15){
            issue(chunk + 1);
            asm volatile("cp.async.wait_group 1;" ::: "memory");
        } else {
            asm volatile("cp.async.wait_group 0;" ::: "memory");
        }
        __syncthreads();
        const float* bufp = &sm.ss[chunk & 1][0][0];

        #pragma unroll
        for (int cc = 0; cc < 8; cc++){
            float4 w4 = sm.sc1[chunk*8 + cc];
            float v0 = bufp[cc*SSROW2 + tid];
            ga0[0] = fmaf(w4.x, v0, ga0[0]);
            ga0[1] = fmaf(w4.y, v0, ga0[1]);
            ga0[2] = fmaf(w4.z, v0, ga0[2]);
            ga0[3] = fmaf(w4.w, v0, ga0[3]);
            if (act1){
                float v1 = bufp[cc*SSROW2 + p1];
                ga1[0] = fmaf(w4.x, v1, ga1[0]);
                ga1[1] = fmaf(w4.y, v1, ga1[1]);
                ga1[2] = fmaf(w4.z, v1, ga1[2]);
                ga1[3] = fmaf(w4.w, v1, ga1[3]);
            }
        }

        float h0 = 0.f, h1 = 0.f, h2 = 0.f, h3 = 0.f;
        if (actH){
            const float* row = bufp + cl*SSROW2 + s12;
            if (hh){
                #pragma unroll
                for (int nl = H1; nl < SPAN; nl++){
                    float  v = row[nl*12];
                    float4 w4 = sm.sc2[nl];
                    h0 = fmaf(w4.x, v, h0);
                    h1 = fmaf(w4.y, v, h1);
                    h2 = fmaf(w4.z, v, h2);
                    h3 = fmaf(w4.w, v, h3);
                }
                sm.hred[rem*4+0] = h0;
                sm.hred[rem*4+1] = h1;
                sm.hred[rem*4+2] = h2;
                sm.hred[rem*4+3] = h3;
            } else {
                #pragma unroll
                for (int nl = 0; nl < H1; nl++){
                    float  v = row[nl*12];
                    float4 w4 = sm.sc2[nl];
                    h0 = fmaf(w4.x, v, h0);
                    h1 = fmaf(w4.y, v, h1);
                    h2 = fmaf(w4.z, v, h2);
                    h3 = fmaf(w4.w, v, h3);
                }
            }
        }
        __syncthreads();
        if (actH && !hh){
            int c = chunk*8 + cl;
            g_Hpart[hp0 + slH*C_ + c] = h0 + sm.hred[rem*4+0];
            g_Hpart[hp1 + slH*C_ + c] = h1 + sm.hred[rem*4+1];
            g_Hpart[hp2 + slH*C_ + c] = h2 + sm.hred[rem*4+2];
            g_Hpart[hp3 + slH*C_ + c] = h3 + sm.hred[rem*4+3];
        }
    }

    if (ch && tid < C_){
        g_Hpart[hp0 + tid] = 0.f;
        g_Hpart[hp1 + tid] = 0.f;
        g_Hpart[hp2 + tid] = 0.f;
        g_Hpart[hp3 + tid] = 0.f;
    }

    // ---- fused GW partial for this n-span ----
    float* sg = &sm.ss[0][0][0];
    #pragma unroll
    for (int i = 0; i < 4; i++){
        sg[i*468 + tid] = ga0[i];
        if (act1) sg[i*468 + tid + 256] = ga1[i];
    }
    __syncthreads();

    {
        int c   = tid & 127;
        int il2 = tid >> 7;
        #pragma unroll
        for (int i0 = 0; i0 < 2; i0++){
            int i = il2*2 + i0;
            const float* wp  = w + (size_t)i*N_*C_ + (size_t)n0*C_ + c;
            const float* sgp = sg + i*468;
            float acc[12];
            #pragma unroll
            for (int s = 0; s < 12; s++) acc[s] = 0.f;
            #pragma unroll 4
            for (int nl = 0; nl < SPAN; nl++){
                float wv  = __ldg(wp + (size_t)nl*C_);
                float4 aa = *(const float4*)(sgp + nl*12);
                float4 bb = *(const float4*)(sgp + nl*12 + 4);
                float4 cc = *(const float4*)(sgp + nl*12 + 8);
                acc[0]  = fmaf(aa.x, wv, acc[0]);
                acc[1]  = fmaf(aa.y, wv, acc[1]);
                acc[2]  = fmaf(aa.z, wv, acc[2]);
                acc[3]  = fmaf(aa.w, wv, acc[3]);
                acc[4]  = fmaf(bb.x, wv, acc[4]);
                acc[5]  = fmaf(bb.y, wv, acc[5]);
                acc[6]  = fmaf(bb.z, wv, acc[6]);
                acc[7]  = fmaf(bb.w, wv, acc[7]);
                acc[8]  = fmaf(cc.x, wv, acc[8]);
                acc[9]  = fmaf(cc.y, wv, acc[9]);
                acc[10] = fmaf(cc.z, wv, acc[10]);
                acc[11] = fmaf(cc.w, wv, acc[11]);
            }
            int base = HPidx(nt,ch,i,b);
            #pragma unroll
            for (int s = 0; s < 12; s++)
                g_GWpart[base + (s + ch)*C_ + c] = acc[s];
            if (ch) g_GWpart[base + c] = 0.f;
        }
    }
}

__global__ void __launch_bounds__(256) kA_kernel(
    const float* __restrict__ XL,  const float* __restrict__ XH,
    const float* __restrict__ c1L, const float* __restrict__ c2L,
    const float* __restrict__ wL,
    const float* __restrict__ c1H, const float* __restrict__ c2H,
    const float* __restrict__ wH)
{
    __shared__ SMa sm;
    int bid = blockIdx.x, tid = threadIdx.x;
    int group = bid >> 3, nt = bid & 7;
    int b = group >> 1, ch = group & 1;
    const float4* X4 = (const float4*)(ch ? XH : XL);
    const float* c1 = ch ? c1H : c1L;
    const float* c2 = ch ? c2H : c2L;
    const float* w  = ch ? wH  : wL;
    int n0 = nt*38 + min(nt, 3);
    if (nt < 3) phaseA<39>(sm, X4, c1, c2, w, b, ch, nt, n0, tid);
    else        phaseA<38>(sm, X4, c1, c2, w, b, ch, nt, n0, tid);
}

// ==================== kReduce: collapse 8 n-tile partials to dense ===========
#define RED_ITEMS (2*4*B_*TMAX*C_/4)   // 106496 float4 per tensor
__global__ void __launch_bounds__(256) kReduce_kernel()
{
    int idx = blockIdx.x*256 + threadIdx.x;      // exact: 416*256 = RED_ITEMS
    const float4* hp = (const float4*)g_Hpart;
    const float4* gp = (const float4*)g_GWpart;
    float4 h = hp[idx], g = gp[idx];
    #pragma unroll
    for (int nt = 1; nt < NTILE; nt++){
        float4 a = hp[idx + nt*RED_ITEMS];
        float4 c = gp[idx + nt*RED_ITEMS];
        h.x += a.x; h.y += a.y; h.z += a.z; h.w += a.w;
        g.x += c.x; g.y += c.y; g.z += c.z; g.w += c.w;
    }
    ((float4*)g_Hd )[idx] = h;
    ((float4*)g_GWd)[idx] = g;
}

// ==================== chain kernel: 4-layer tiny attention ===================
#define CTHREADS 512

// GWs/Hs first: 16B-aligned for STS.128 (TMAX*PADC = 1716 floats, %4 == 0)
struct __align__(16) SMchain {
    float GWs[2][TMAX*PADC], Hs[2][TMAX*PADC];
    float f1w[TMAX*PADC], f2s[TMAX*PADC];
    float A[TMAX*TMAX], A2[TMAX*TMAX];
    float sS[TMAX*TMAX], slog[TMAX*TMAX], mu[TMAX], isd[TMAX];
};

template<int T>
__device__ __forceinline__ void load_layer(
    SMchain& sm, int bufi, int ch, int b, int i, int tid)
{
    const int items4 = T*C_/4;                  // 384 / 416
    if (tid < items4){
        int base4 = HDidx(ch,i,b) >> 2;         // HDidx is a multiple of 1664
        int s = tid >> 5, c = (tid & 31) << 2;  // C_/4 = 32 float4 per row
        float4 h  = ((const float4*)g_Hd )[base4 + tid];
        float4 gw = ((const float4*)g_GWd)[base4 + tid];
        *(float4*)&sm.Hs [bufi][s*PADC + c] = h;
        *(float4*)&sm.GWs[bufi][s*PADC + c] = gw;
    }
}

template<int T>
__device__ __forceinline__ void chain_impl(
    SMchain& sm, int ch, int b,
    const float* __restrict__ bias, const float* __restrict__ vvp,
    const float* __restrict__ gam,  const float* __restrict__ bet,
    int tid)
{
    if (tid < T*T){
        int s = tid / T, t = tid - (tid/T)*T;
        sm.A[s*TMAX + t] = (s == t) ? 1.f : 0.f;
    }
    load_layer<T>(sm, 0, ch, b, 0, tid);
    __syncthreads();

    #pragma unroll
    for (int i = 0; i < LAYERS; i++){
        int bufi = i & 1;
        const float* GWs = sm.GWs[bufi];
        const float* Hs  = sm.Hs [bufi];

        #pragma unroll
        for (int o0 = 0; o0 < T*C_; o0 += CTHREADS){
            int o = o0 + tid;
            if (o < T*C_){
                int t = o / C_, c = o - (o/C_)*C_;
                float a1 = 0.f, a2 = 0.f;
                #pragma unroll
                for (int s = 0; s < T; s++){
                    float a = sm.A[s*TMAX + t];
                    a1 = fmaf(a, GWs[s*PADC + c], a1);
                    a2 = fmaf(a, Hs [s*PADC + c], a2);
                }
                sm.f1w[t*PADC + c] = a1;
                sm.f2s[t*PADC + c] = a2;
            }
        }
        __syncthreads();

        // scores: 4 independent accumulator chains
        if (tid < T*T){
            int t = tid / T, q = tid - (tid/T)*T;
            const float* f1p = &sm.f1w[t*PADC];
            const float* f2p = &sm.f2s[q*PADC];
            float a0 = 0.f, a1 = 0.f, a2 = 0.f, a3 = 0.f;
            #pragma unroll 8
            for (int c0 = 0; c0 < C_; c0 += 4){
                a0 = fmaf(f1p[c0],   f2p[c0],   a0);
                a1 = fmaf(f1p[c0+1], f2p[c0+1], a1);
                a2 = fmaf(f1p[c0+2], f2p[c0+2], a2);
                a3 = fmaf(f1p[c0+3], f2p[c0+3], a3);
            }
            float acc = bias[(i*T + t)*T + q] + ((a0 + a1) + (a2 + a3));
            sm.sS[t*TMAX + q] = 1.f / (1.f + __expf(-acc));
        }
        __syncthreads();

        int buf = i & 1;
        if (tid < T*T){
            int t = tid / T, q = tid - (tid/T)*T;
            float acc = 0.f;
            #pragma unroll
            for (int k = 0; k < T; k++)
                acc = fmaf(vvp[(i*T + t)*T + k], sm.sS[k*TMAX + q], acc);
            sm.slog[t*TMAX + q] = acc;
            g_logits[buf][((ch*B_ + b)*TMAX + t)*TMAX + q] = acc;
        }

        if (i < LAYERS-1)
            load_layer<T>(sm, (i+1)&1, ch, b, i+1, tid);

        barrier64();

        {
            int w = tid >> 5, lane = tid & 31;
            if (w < T){
                int q = w;
                float sum = 0.f, sq = 0.f;
                #pragma unroll 4
                for (int j = lane; j < B_*T; j += 32){
                    int bb = j / T, t = j - (j/T)*T;
                    float val = __ldcg(&g_logits[buf][((ch*B_ + bb)*TMAX + t)*TMAX + q]);
                    sum += val; sq += val*val;
                }
                #pragma unroll
                for (int off = 16; off; off >>= 1){
                    sum += __shfl_down_sync(0xffffffff, sum, off);
                    sq  += __shfl_down_sync(0xffffffff, sq,  off);
                }
                if (lane == 0){
                    const float cnt = (float)(B_*T);
                    float m = sum / cnt;
                    float var = sq / cnt - m*m;
                    sm.mu[q]  = m;
                    sm.isd[q] = rsqrtf(var + BN_EPS);
                }
            }
        }
        __syncthreads();

        if (tid < T){
            int t = tid;
            float z[T];
            float mx = -1e30f;
            #pragma unroll
            for (int q = 0; q < T; q++){
                float val = (sm.slog[t*TMAX + q] - sm.mu[q]) * sm.isd[q]
                            * gam[i*T + q] + bet[i*T + q];
                z[q] = val;
                mx = fmaxf(mx, val);
            }
            float sum = 0.f;
            #pragma unroll
            for (int q = 0; q < T; q++){ z[q] = __expf(z[q] - mx); sum += z[q]; }
            float inv = 1.f / sum;
            #pragma unroll
            for (int q = 0; q < T; q++) sm.sS[t*TMAX + q] = z[q] * inv;
        }
        __syncthreads();

        if (tid < T*T){
            int s = tid / T, q = tid - (tid/T)*T;
            float acc = 0.f;
            #pragma unroll
            for (int t = 0; t < T; t++)
                acc = fmaf(sm.A[s*TMAX + t], sm.sS[q*TMAX + t], acc);
            sm.A2[s*TMAX + q] = acc;
        }
        __syncthreads();
        if (tid < T*T){
            int s = tid / T, q = tid - (tid/T)*T;
            sm.A[s*TMAX + q] = sm.A2[s*TMAX + q];
        }
        __syncthreads();
    }

    if (tid < T)
        g_avec[(ch*B_ + b)*TMAX + tid] = sm.A[tid*TMAX + (T-1)];
}

__global__ void __launch_bounds__(CTHREADS) chain_kernel(
    const float* __restrict__ bL, const float* __restrict__ vL,
    const float* __restrict__ gL, const float* __restrict__ beL,
    const float* __restrict__ bH, const float* __restrict__ vH,
    const float* __restrict__ gH, const float* __restrict__ beH)
{
    __shared__ SMchain sm;
    int bid = blockIdx.x, tid = threadIdx.x;
    int ch = bid & 1, b = bid >> 1;
    if (ch == 0) chain_impl<TL>(sm, 0, b, bL, vL, gL, beL, tid);
    else         chain_impl<TH>(sm, 1, b, bH, vH, gH, beH, tid);
}

// ==================== final kernel: residual + alpha mix =====================
__global__ void __launch_bounds__(256) final_kernel(
    const float* __restrict__ XL, const float* __restrict__ XH,
    const float* __restrict__ alpha, float* __restrict__ out)
{
    int r = blockIdx.x*blockDim.x + threadIdx.x;
    if (r >= B_*C_*N_) return;
    int b = r / (C_*N_);

    const float4* xl4 = (const float4*)(XL + (size_t)r*TL);
    const float4* xh4 = (const float4*)(XH + (size_t)r*TL);
    float4 l0 = xl4[0], l1 = xl4[1], l2 = xl4[2];
    float4 h0 = xh4[0], h1 = xh4[1], h2 = xh4[2];

    const float* aL = &g_avec[b*TMAX];
    const float* aH = &g_avec[(B_ + b)*TMAX];

    float accL = l2.w;
    accL = fmaf(l0.x, __ldg(aL+0),  accL);
    accL = fmaf(l0.y, __ldg(aL+1),  accL);
    accL = fmaf(l0.z, __ldg(aL+2),  accL);
    accL = fmaf(l0.w, __ldg(aL+3),  accL);
    accL = fmaf(l1.x, __ldg(aL+4),  accL);
    accL = fmaf(l1.y, __ldg(aL+5),  accL);
    accL = fmaf(l1.z, __ldg(aL+6),  accL);
    accL = fmaf(l1.w, __ldg(aL+7),  accL);
    accL = fmaf(l2.x, __ldg(aL+8),  accL);
    accL = fmaf(l2.y, __ldg(aL+9),  accL);
    accL = fmaf(l2.z, __ldg(aL+10), accL);
    accL = fmaf(l2.w, __ldg(aL+11), accL);

    float accH = h2.w;
    accH = fmaf(h0.x, __ldg(aH+1),  accH);
    accH = fmaf(h0.y, __ldg(aH+2),  accH);
    accH = fmaf(h0.z, __ldg(aH+3),  accH);
    accH = fmaf(h0.w, __ldg(aH+4),  accH);
    accH = fmaf(h1.x, __ldg(aH+5),  accH);
    accH = fmaf(h1.y, __ldg(aH+6),  accH);
    accH = fmaf(h1.z, __ldg(aH+7),  accH);
    accH = fmaf(h1.w, __ldg(aH+8),  accH);
    accH = fmaf(h2.x, __ldg(aH+9),  accH);
    accH = fmaf(h2.y, __ldg(aH+10), accH);
    accH = fmaf(h2.z, __ldg(aH+11), accH);
    accH = fmaf(h2.w, __ldg(aH+12), accH);

    float sa = 1.f / (1.f + expf(-alpha[0]));
    out[r] = sa*accL + (1.f - sa)*accH;
}

// ---------------- launch ----------------------------------------------------
extern "C" void kernel_launch(void* const* d_in, const int* in_sizes, int n_in,
                              void* d_out, int out_size)
{
    const float* XL  = (const float*)d_in[0];
    const float* XH  = (const float*)d_in[1];
    const float* lc1 = (const float*)d_in[2];
    const float* lc2 = (const float*)d_in[3];
    const float* lw  = (const float*)d_in[4];
    const float* lb  = (const float*)d_in[5];
    const float* lv  = (const float*)d_in[6];
    const float* lg  = (const float*)d_in[7];
    const float* lbe = (const float*)d_in[8];
    const float* hc1 = (const float*)d_in[9];
    const float* hc2 = (const float*)d_in[10];
    const float* hw  = (const float*)d_in[11];
    const float* hb  = (const float*)d_in[12];
    const float* hv  = (const float*)d_in[13];
    const float* hg  = (const float*)d_in[14];
    const float* hbe = (const float*)d_in[15];
    const float* alpha = (const float*)d_in[16];
    float* out = (float*)d_out;

    kA_kernel     <<<512, 256>>>(XL, XH, lc1, lc2, lw, hc1, hc2, hw);
    kReduce_kernel<<<RED_ITEMS/256, 256>>>();
    chain_kernel  <<<NCHAIN, CTHREADS>>>(lb, lv, lg, lbe, hb, hv, hg, hbe);
    int tot = B_*C_*N_;
    final_kernel  <<<(tot + 255)/256, 256>>>(XL, XH, alpha, out);
}